// round 14
// baseline (speedup 1.0000x reference)
#include <cuda_runtime.h>

typedef unsigned int       u32;
typedef unsigned long long u64;

#define NB   2
#define NN   512
#define IND  512
#define MEMD 300
#define HIDD 64
#define CDIM 428
#define NEG_SLOPE 0.01f
#define GRIDSZ 148
#define NTHR 512
#define NSTREAM (4 * GRIDSZ)      // 128-thread quarter streams
#define TI 32
#define TJ 128

// ---------------- scratch (allocation-free: __device__ globals) -------------
__device__ float g_B1[IND * CDIM];        // [w0 | Wp0]
__device__ float g_B2[MEMD * CDIM];       // [w1 | Wp1]
__device__ float g_bias1[CDIM];
__device__ float g_bias2[CDIM];
__device__ float g_hs[NB * NN * CDIM];    // [h(300) | si(64) | sj(64)]
__device__ float g_out1[NB * NN * MEMD];
__device__ float g_q0[NB * NN * MEMD];    // out-GEMM K-split partials
__device__ float g_q1[NB * NN * MEMD];
__device__ float g_p[NB * NN * NN];
__device__ float g_partial[NB * 64];
__device__ unsigned g_bar_count;          // zero-init
__device__ unsigned g_bar_gen;            // monotonic across replays

// ---------------- grid-wide barrier (replay-safe; R10-proven) ----------------
__device__ __forceinline__ void grid_bar(unsigned target)
{
    __threadfence();
    __syncthreads();
    if (threadIdx.x == 0) {
        if (atomicAdd(&g_bar_count, 1u) == GRIDSZ - 1u) {
            g_bar_count = 0u;
            __threadfence();
            *(volatile unsigned*)&g_bar_gen = target;
        } else {
            while ((int)(*(volatile unsigned*)&g_bar_gen - target) < 0) { }
        }
        __threadfence();
    }
    __syncthreads();
}

// per-quarter named barrier (128 threads; ids 1..4)
__device__ __forceinline__ void qbar(int q)
{
    asm volatile("bar.sync %0, 128;" :: "r"(q + 1) : "memory");
}

// ---------------- cp.async + packed f32 helpers ------------------------------
__device__ __forceinline__ void cpa16(u32 dst, const void* src, bool p)
{
    if (p) asm volatile("cp.async.ca.shared.global [%0], [%1], 16;"
                        :: "r"(dst), "l"(src));
    else   asm volatile("st.shared.v4.b32 [%0], {%1,%1,%1,%1};"
                        :: "r"(dst), "r"(0u));
}
__device__ __forceinline__ void cpa8(u32 dst, const void* src, bool p)
{
    if (p) asm volatile("cp.async.ca.shared.global [%0], [%1], 8;"
                        :: "r"(dst), "l"(src));
    else   asm volatile("st.shared.v2.b32 [%0], {%1,%1};"
                        :: "r"(dst), "r"(0u));
}
__device__ __forceinline__ void cpa_commit()
{
    asm volatile("cp.async.commit_group;" ::: "memory");
}
__device__ __forceinline__ void cpa_wait1()
{
    asm volatile("cp.async.wait_group 1;" ::: "memory");
}
__device__ __forceinline__ void cpa_wait0()
{
    asm volatile("cp.async.wait_group 0;" ::: "memory");
}
__device__ __forceinline__ u64 packff(float x, float y)
{
    u64 r;
    asm("mov.b64 %0, {%1, %2};" : "=l"(r)
        : "r"(__float_as_uint(x)), "r"(__float_as_uint(y)));
    return r;
}
__device__ __forceinline__ void fma2(u64& d, u64 a, u64 b)
{
    asm("fma.rn.f32x2 %0, %1, %2, %3;" : "=l"(d) : "l"(a), "l"(b), "l"(d));
}
__device__ __forceinline__ float2 unpk(u64 v)
{
    u32 lo, hi;
    asm("mov.b64 {%0, %1}, %2;" : "=r"(lo), "=r"(hi) : "l"(v));
    return make_float2(__uint_as_float(lo), __uint_as_float(hi));
}
__device__ __forceinline__ void lds_v2u64(u64& x, u64& y, const float* p)
{
    u32 a = (u32)__cvta_generic_to_shared(p);
    asm volatile("ld.shared.v2.b64 {%0, %1}, [%2];"
                 : "=l"(x), "=l"(y) : "r"(a));
}

// ---------------- dynamic smem layout ----------------------------------------
// per quarter: 2 stages x (A 16x66 f = 4224B | B 64x64 f = 16384B) = 41216
// pair overlay (offset 0, spans quarters 0-1):
//   SiT2[64][17]f2 8704 | SjT[64][129] 33024 | W 256 | red 2048 | cvi 128 | cvj 512
#define SM_A_BYTES 4224
#define SM_STAGE   20608
#define SM_QUARTER 41216
#define SM_SJ      8704
#define SM_W       41728
#define SM_RED     41984
#define SM_CVI     44032
#define SM_CVJ     44160
#define SM_INVZ    (4 * SM_QUARTER)
#define SM_DYN     (SM_INVZ + 128)

// ---------------- cp.async GEMM (quarter streams) ----------------------------
// 128-thread quarter computes 16x64 tiles, BK=64, 2-stage pipeline,
// 1x8 micro with packed f32x2 FMAs. KSPLIT=2 -> unscaled partials C0/C1.
template<int BVIEW, int KSPLIT>
__device__ void gemm_cp(char* SMD, int q, int qid,
                        const float* __restrict__ A, long long sA, int ldA,
                        const float* __restrict__ B, long long sB, int ldB,
                        float* __restrict__ C0, float* __restrict__ C1,
                        long long sC, int ldC,
                        int M, int Ncols, int K, int batches,
                        const float* __restrict__ bias)
{
    char* qb = SMD + q * SM_QUARTER;
    u32 qb32 = (u32)__cvta_generic_to_shared(qb);
    int lid = threadIdx.x & 127;
    int tx = lid & 7, ty = lid >> 3;          // 8 x 16: row ty, cols 2 groups

    int colT = (Ncols + 63) >> 6;
    int rowT = (M + 15) >> 4;
    int TT   = colT * rowT * batches * KSPLIT;
    int Klen = K / KSPLIT;
    int nkt  = (Klen + 63) >> 6;

    for (int t = qid; t < TT; t += NSTREAM) {
        int ks = (KSPLIT == 2) ? (t & 1) : 0;
        int t2 = (KSPLIT == 2) ? (t >> 1) : t;
        int bz  = t2 / (colT * rowT);
        int r2  = t2 - bz * (colT * rowT);
        int byy = r2 / colT, bxx = r2 - byy * colT;
        int row0 = byy * 16, col0 = bxx * 64;
        int kbase = ks * Klen;

        const float* Ab = A + (long long)bz * sA;
        const float* Bb;
        int colB;
        if (BVIEW) { Bb = B + (col0 >= 64 ? MEMD * 64 : 0); colB = col0 & 63; }
        else       { Bb = B + (long long)bz * sB;           colB = col0; }
        float* Cb = (ks ? C1 : C0) + (long long)bz * sC;

        auto issue = [&](int stage, int kt) {
            u32 sb = qb32 + stage * SM_STAGE;
            int kg = kbase + kt * 64;
            #pragma unroll
            for (int g = 0; g < 4; g++) {          // A: 16 rows x 64 k, 8B chunks
                int idx = lid + g * 128;
                int rr = idx >> 5, kc = (idx & 31) * 2;
                int k = kg + kc;
                bool p = (k < K) && (row0 + rr < M);
                cpa8(sb + rr * 264 + kc * 4,
                     Ab + (long long)(row0 + rr) * ldA + k, p);
            }
            #pragma unroll
            for (int g = 0; g < 8; g++) {          // B: 64 k x 64 cols, 16B chunks
                int idx = lid + g * 128;
                int kk = idx >> 4, c4 = (idx & 15) * 4;
                int k = kg + kk;
                bool p = (k < K) && (col0 + c4 < Ncols);
                cpa16(sb + SM_A_BYTES + kk * 256 + c4 * 4,
                      Bb + (long long)k * ldB + colB + c4, p);
            }
            cpa_commit();
        };

        issue(0, 0);

        u64 acc0 = 0, acc1 = 0, acc2 = 0, acc3 = 0;

        for (int kt = 0; kt < nkt; kt++) {
            bool more = (kt + 1 < nkt);
            if (more) issue((kt + 1) & 1, kt + 1);
            if (more) cpa_wait1(); else cpa_wait0();
            qbar(q);

            const float* Asf = (const float*)(qb + (kt & 1) * SM_STAGE);
            const float* Bsf = Asf + SM_A_BYTES / 4;
            #pragma unroll 8
            for (int kp = 0; kp < 32; kp++) {
                float2 a = *(const float2*)&Asf[ty * 66 + kp * 2];
                u64 b00a, b00b, b01a, b01b, b10a, b10b, b11a, b11b;
                lds_v2u64(b00a, b00b, &Bsf[(kp * 2) * 64 + tx * 4]);
                lds_v2u64(b01a, b01b, &Bsf[(kp * 2) * 64 + 32 + tx * 4]);
                lds_v2u64(b10a, b10b, &Bsf[(kp * 2 + 1) * 64 + tx * 4]);
                lds_v2u64(b11a, b11b, &Bsf[(kp * 2 + 1) * 64 + 32 + tx * 4]);
                u64 ax = packff(a.x, a.x), ay = packff(a.y, a.y);
                fma2(acc0, ax, b00a); fma2(acc1, ax, b00b);
                fma2(acc2, ax, b01a); fma2(acc3, ax, b01b);
                fma2(acc0, ay, b10a); fma2(acc1, ay, b10b);
                fma2(acc2, ay, b11a); fma2(acc3, ay, b11b);
            }
            qbar(q);
        }

        // epilogue: row ty; cols col0 + g*32 + tx*4 + {0..3}
        int row = row0 + ty;
        if (row < M) {
            #pragma unroll
            for (int g = 0; g < 2; g++) {
                int cbase = col0 + g * 32 + tx * 4;
                float2 lo = unpk(g ? acc2 : acc0);
                float2 hi = unpk(g ? acc3 : acc1);
                float v[4] = {lo.x, lo.y, hi.x, hi.y};
                #pragma unroll
                for (int j = 0; j < 4; j++) {
                    int cc = cbase + j;
                    if (cc < Ncols) {
                        float bv = bias ? bias[cc] : 0.f;
                        Cb[(long long)row * ldC + cc] = v[j] + bv;
                    }
                }
            }
        }
    }
}

// ---------------- pairwise: p = adj*exp(leaky(e)), partial Z -----------------
// e = 0.5*(ci + dj + sum_h w_h*|si_h + sj_h|) + a2b   (relu(x) = (x+|x|)/2)
__device__ void pair_phase(char* SMD,
                           const float* __restrict__ adj,
                           const float* __restrict__ a2w,
                           const float* __restrict__ a2b)
{
    float2 (*SiT2)[17]    = (float2(*)[17])SMD;                 // [64][17]
    float  (*SjT)[TJ + 1] = (float(*)[TJ + 1])(SMD + SM_SJ);    // [64][129]
    float* W   = (float*)(SMD + SM_W);
    float* red = (float*)(SMD + SM_RED);
    float2* cvi = (float2*)(SMD + SM_CVI);    // [16] rank-1 i-terms
    float*  cvj = (float*)(SMD + SM_CVJ);     // [128] rank-1 j-terms

    int tid = threadIdx.x;
    int tx = tid & 31, ty = (tid >> 5) & 15;
    const int Tt = NB * (NN / TI) * (NN / TJ);   // 128

    for (int t = blockIdx.x; t < Tt; t += GRIDSZ) {
        int b = t >> 6;
        int rem = t & 63;
        int by = rem >> 2, bx = rem & 3;
        int i0 = by * TI, j0 = bx * TJ;

        __syncthreads();
        for (int idx = tid; idx < HIDD * 16; idx += NTHR) {
            int h = idx & 63, rr = idx >> 6;
            float u0 = g_hs[((long long)(b * NN) + i0 + rr) * CDIM + 300 + h];
            float u1 = g_hs[((long long)(b * NN) + i0 + rr + 16) * CDIM + 300 + h];
            SiT2[h][rr] = make_float2(u0, u1);
        }
        for (int idx = tid; idx < HIDD * TJ; idx += NTHR) {
            int h = idx & 63, rr = idx >> 6;
            SjT[h][rr] = g_hs[((long long)(b * NN) + j0 + rr) * CDIM + 364 + h];
        }
        if (tid < HIDD) W[tid] = a2w[tid];
        __syncthreads();

        // rank-1 prologue: dj (128 dots, tid<128) + ci (16 f2 dots, tid 128..143)
        if (tid < 128) {
            float s = 0.f;
            #pragma unroll 8
            for (int h = 0; h < HIDD; h++) s += W[h] * SjT[h][tid];
            cvj[tid] = s;
        } else if (tid < 144) {
            int r = tid - 128;                // r in [0,16)
            float sx = 0.f, sy = 0.f;
            #pragma unroll 8
            for (int h = 0; h < HIDD; h++) {
                float2 v = SiT2[h][r];
                float w = W[h];
                sx += w * v.x; sy += w * v.y;
            }
            cvi[r] = make_float2(sx, sy);
        }
        __syncthreads();

        float acc[8] = {0.f, 0.f, 0.f, 0.f, 0.f, 0.f, 0.f, 0.f};
        #pragma unroll 8
        for (int h = 0; h < HIDD; h++) {
            float w = W[h];
            float2 ai = SiT2[h][ty];
            float bj[4];
            #pragma unroll
            for (int jj = 0; jj < 4; jj++) bj[jj] = SjT[h][tx + 32 * jj];
            #pragma unroll
            for (int jj = 0; jj < 4; jj++) {
                acc[jj]     += w * fabsf(ai.x + bj[jj]);
                acc[4 + jj] += w * fabsf(ai.y + bj[jj]);
            }
        }

        float a2bv = a2b[0];
        float2 civ = cvi[ty];
        float psum = 0.f;
        int ia = i0 + ty, ib = i0 + ty + 16;
        #pragma unroll
        for (int jj = 0; jj < 4; jj++) {
            int j = j0 + tx + 32 * jj;
            float dj = cvj[tx + 32 * jj];
            float e0 = 0.5f * (acc[jj]     + civ.x + dj) + a2bv;
            float e1 = 0.5f * (acc[4 + jj] + civ.y + dj) + a2bv;
            e0 = e0 > 0.f ? e0 : NEG_SLOPE * e0;
            e1 = e1 > 0.f ? e1 : NEG_SLOPE * e1;
            float ad0 = adj[((long long)b * NN + ia) * NN + j];
            float ad1 = adj[((long long)b * NN + ib) * NN + j];
            float p0 = ad0 * __expf(e0);
            float p1 = ad1 * __expf(e1);
            g_p[((long long)b * NN + ia) * NN + j] = p0;
            g_p[((long long)b * NN + ib) * NN + j] = p1;
            psum += p0 + p1;
        }

        red[tid] = psum;
        __syncthreads();
        for (int s = 256; s > 0; s >>= 1) {
            if (tid < s) red[tid] += red[tid + s];
            __syncthreads();
        }
        if (tid == 0) g_partial[b * 64 + rem] = red[0];
    }
}

// ---------------- combine: dst = (q0+q1) * invZ[b] ---------------------------
__device__ void combine_phase(char* SMD, const float* __restrict__ q0,
                              const float* __restrict__ q1,
                              float* __restrict__ dst)
{
    float* invZ = (float*)(SMD + SM_INVZ);
    int tid = threadIdx.x;
    if (tid < NB) {
        float s = 0.f;
        #pragma unroll
        for (int k = 0; k < 64; k++) s += g_partial[tid * 64 + k];
        invZ[tid] = 1.f / s;
    }
    __syncthreads();
    float z0 = invZ[0], z1 = invZ[1];
    const int TOT = NB * NN * MEMD;
    for (int i = blockIdx.x * NTHR + tid; i < TOT; i += GRIDSZ * NTHR) {
        float z = (i < NN * MEMD) ? z0 : z1;
        dst[i] = (q0[i] + q1[i]) * z;
    }
}

// ---------------- the one persistent kernel ----------------------------------
__global__ void __launch_bounds__(NTHR, 1) fused_gat(
    const float* __restrict__ feature, const float* __restrict__ adj,
    const float* __restrict__ w0, const float* __restrict__ b0,
    const float* __restrict__ w1, const float* __restrict__ b1,
    const float* __restrict__ a1w, const float* __restrict__ a1b,
    const float* __restrict__ a2w, const float* __restrict__ a2b,
    float* __restrict__ out)
{
    extern __shared__ char SMD[];
    __shared__ unsigned s_base;
    if (threadIdx.x == 0) s_base = *(volatile unsigned*)&g_bar_gen;
    __syncthreads();
    unsigned bb = s_base;
    int q   = threadIdx.x >> 7;               // quarter 0..3
    int qid = q * GRIDSZ + blockIdx.x;        // 0..591
    int tid = threadIdx.x;

    // ======== P0: B' = [W | W@a1w-packed], bias vectors ========
    for (int idx = blockIdx.x * NTHR + tid; idx < IND * MEMD; idx += GRIDSZ * NTHR) {
        int r = idx / MEMD, c = idx - r * MEMD;
        g_B1[r * CDIM + c] = w0[idx];
    }
    for (int idx = blockIdx.x * NTHR + tid; idx < MEMD * MEMD; idx += GRIDSZ * NTHR) {
        int r = idx / MEMD, c = idx - r * MEMD;
        g_B2[r * CDIM + c] = w1[idx];
    }
    if (blockIdx.x < 2) {
        const float* bsrc = blockIdx.x ? b1 : b0;
        float* bd = blockIdx.x ? g_bias2 : g_bias1;
        for (int c = tid; c < MEMD; c += NTHR) bd[c] = bsrc[c];
        if (tid < 128) {
            float acc = 0.f;
            for (int k = 0; k < MEMD; k++) {
                float w = (tid < 64) ? a1w[k * 64 + tid]
                                     : a1w[(MEMD + k) * 64 + (tid - 64)];
                acc += bsrc[k] * w;
            }
            bd[300 + tid] = acc + ((tid >= 64) ? a1b[tid - 64] : 0.f);
        }
    }
    // Wp0 on low quarters, Wp1 on high quarters (disjoint)
    gemm_cp<1, 1>(SMD, q, qid, w0, 0, MEMD, a1w, 0, 64,
                  g_B1 + 300, nullptr, 0, CDIM, IND, 128, MEMD, 1, nullptr);
    gemm_cp<1, 1>(SMD, q, (NSTREAM - 1) - qid, w1, 0, MEMD, a1w, 0, 64,
                  g_B2 + 300, nullptr, 0, CDIM, MEMD, 128, MEMD, 1, nullptr);
    grid_bar(bb + 1);

    // ======== layer 1 ========
    gemm_cp<0, 1>(SMD, q, qid, feature, 0, IND, g_B1, 0, CDIM,
                  g_hs, nullptr, 0, CDIM, NB * NN, CDIM, IND, 1, g_bias1);
    grid_bar(bb + 2);
    pair_phase(SMD, adj, a2w, a2b);
    grid_bar(bb + 3);
    gemm_cp<0, 2>(SMD, q, qid, g_p, (long long)NN * NN, NN,
                  g_hs, (long long)NN * CDIM, CDIM,
                  g_q0, g_q1, (long long)NN * MEMD, MEMD,
                  NN, MEMD, NN, NB, nullptr);
    grid_bar(bb + 4);
    combine_phase(SMD, g_q0, g_q1, g_out1);
    grid_bar(bb + 5);

    // ======== layer 2 ========
    gemm_cp<0, 1>(SMD, q, qid, g_out1, 0, MEMD, g_B2, 0, CDIM,
                  g_hs, nullptr, 0, CDIM, NB * NN, CDIM, MEMD, 1, g_bias2);
    grid_bar(bb + 6);
    pair_phase(SMD, adj, a2w, a2b);
    grid_bar(bb + 7);
    gemm_cp<0, 2>(SMD, q, qid, g_p, (long long)NN * NN, NN,
                  g_hs, (long long)NN * CDIM, CDIM,
                  g_q0, g_q1, (long long)NN * MEMD, MEMD,
                  NN, MEMD, NN, NB, nullptr);
    grid_bar(bb + 8);
    combine_phase(SMD, g_q0, g_q1, out);
}

// ---------------- host launcher ----------------------------------------------
extern "C" void kernel_launch(void* const* d_in, const int* in_sizes, int n_in,
                              void* d_out, int out_size)
{
    const float* feature = (const float*)d_in[0];
    const float* adj     = (const float*)d_in[1];
    const float* w0      = (const float*)d_in[2];
    const float* b0      = (const float*)d_in[3];
    const float* w1      = (const float*)d_in[4];
    const float* b1      = (const float*)d_in[5];
    const float* a1w     = (const float*)d_in[6];
    const float* a1b     = (const float*)d_in[7];
    const float* a2w     = (const float*)d_in[8];
    const float* a2b     = (const float*)d_in[9];
    float* out = (float*)d_out;

    static bool attr_set = false;
    if (!attr_set) {
        cudaFuncSetAttribute(fused_gat,
                             cudaFuncAttributeMaxDynamicSharedMemorySize, SM_DYN);
        attr_set = true;
    }
    fused_gat<<<GRIDSZ, NTHR, SM_DYN>>>(feature, adj, w0, b0, w1, b1,
                                        a1w, a1b, a2w, a2b, out);
}

// round 15
// speedup vs baseline: 1.2291x; 1.2291x over previous
#include <cuda_runtime.h>

typedef unsigned int       u32;
typedef unsigned long long u64;

#define NB   2
#define NN   512
#define IND  512
#define MEMD 300
#define HIDD 64
#define CDIM 428
#define NEG_SLOPE 0.01f
#define GRIDSZ 148
#define NTHR 512
#define NSTREAM (4 * GRIDSZ)      // 128-thread quarter streams
#define TI 32
#define TJ 128

// ---------------- scratch (allocation-free: __device__ globals) -------------
__device__ float g_B1[IND * CDIM];        // [w0 | Wp0]
__device__ float g_B2[MEMD * CDIM];       // [w1 | Wp1]
__device__ float g_bias1[CDIM];
__device__ float g_bias2[CDIM];
__device__ float g_hs[NB * NN * CDIM];    // [h(300) | si(64) | sj(64)]
__device__ float g_out1[NB * NN * MEMD];
__device__ float g_q0[NB * NN * CDIM];    // K-split partials (enlarged)
__device__ float g_q1[NB * NN * CDIM];
__device__ float g_p[NB * NN * NN];
__device__ float g_partial[NB * 64];
__device__ unsigned g_bar_count;          // zero-init
__device__ unsigned g_bar_gen;            // monotonic across replays

// ---------------- grid-wide barrier (replay-safe; R10-proven) ----------------
__device__ __forceinline__ void grid_bar(unsigned target)
{
    __threadfence();
    __syncthreads();
    if (threadIdx.x == 0) {
        if (atomicAdd(&g_bar_count, 1u) == GRIDSZ - 1u) {
            g_bar_count = 0u;
            __threadfence();
            *(volatile unsigned*)&g_bar_gen = target;
        } else {
            while ((int)(*(volatile unsigned*)&g_bar_gen - target) < 0) { }
        }
        __threadfence();
    }
    __syncthreads();
}

// per-quarter named barrier (128 threads; ids 1..4)
__device__ __forceinline__ void qbar(int q)
{
    asm volatile("bar.sync %0, 128;" :: "r"(q + 1) : "memory");
}

// ---------------- cp.async + packed f32 helpers ------------------------------
__device__ __forceinline__ void cpa16(u32 dst, const void* src, bool p)
{
    if (p) asm volatile("cp.async.ca.shared.global [%0], [%1], 16;"
                        :: "r"(dst), "l"(src));
    else   asm volatile("st.shared.v4.b32 [%0], {%1,%1,%1,%1};"
                        :: "r"(dst), "r"(0u));
}
__device__ __forceinline__ void cpa8(u32 dst, const void* src, bool p)
{
    if (p) asm volatile("cp.async.ca.shared.global [%0], [%1], 8;"
                        :: "r"(dst), "l"(src));
    else   asm volatile("st.shared.v2.b32 [%0], {%1,%1};"
                        :: "r"(dst), "r"(0u));
}
__device__ __forceinline__ void cpa_commit()
{
    asm volatile("cp.async.commit_group;" ::: "memory");
}
__device__ __forceinline__ void cpa_wait1()
{
    asm volatile("cp.async.wait_group 1;" ::: "memory");
}
__device__ __forceinline__ void cpa_wait0()
{
    asm volatile("cp.async.wait_group 0;" ::: "memory");
}
__device__ __forceinline__ u64 packff(float x, float y)
{
    u64 r;
    asm("mov.b64 %0, {%1, %2};" : "=l"(r)
        : "r"(__float_as_uint(x)), "r"(__float_as_uint(y)));
    return r;
}
__device__ __forceinline__ void fma2(u64& d, u64 a, u64 b)
{
    asm("fma.rn.f32x2 %0, %1, %2, %3;" : "=l"(d) : "l"(a), "l"(b), "l"(d));
}
__device__ __forceinline__ float2 unpk(u64 v)
{
    u32 lo, hi;
    asm("mov.b64 {%0, %1}, %2;" : "=r"(lo), "=r"(hi) : "l"(v));
    return make_float2(__uint_as_float(lo), __uint_as_float(hi));
}
__device__ __forceinline__ void lds_v2u64(u64& x, u64& y, const float* p)
{
    u32 a = (u32)__cvta_generic_to_shared(p);
    asm volatile("ld.shared.v2.b64 {%0, %1}, [%2];"
                 : "=l"(x), "=l"(y) : "r"(a));
}

// ---------------- dynamic smem layout ----------------------------------------
// per quarter: 2 stages x (A 32x66 f = 8448B | B 64x64 f = 16384B) = 49664
// pair overlay (offset 0, spans quarters 0-1):
//   SiT2[64][17]f2 8704 | SjT[64][132] 33792 | W 256 | red 2048 | cvi 128 | cvj 512
#define SM_A_BYTES 8448
#define SM_STAGE   24832
#define SM_QUARTER 49664
#define SM_SJ      8704
#define SM_W       42496
#define SM_RED     42752
#define SM_CVI     44800
#define SM_CVJ     44928
#define SM_INVZ    (4 * SM_QUARTER)
#define SM_DYN     (SM_INVZ + 256)

// ---------------- cp.async GEMM (quarter streams; R10-proven 32x64) ----------
// 128-thread quarter computes 32x64 tiles, BK=64, 2-stage pipeline,
// 2x8 micro with packed f32x2 FMAs. KSPLIT=2 -> unscaled partials C0/C1.
// NOTE: k guards use kend = kbase + Klen (correct for Klen % 64 != 0).
template<int BVIEW, int KSPLIT>
__device__ void gemm_cp(char* SMD, int q, int qid,
                        const float* __restrict__ A, long long sA, int ldA,
                        const float* __restrict__ B, long long sB, int ldB,
                        float* __restrict__ C0, float* __restrict__ C1,
                        long long sC, int ldC,
                        int M, int Ncols, int K, int batches,
                        const float* __restrict__ bias)
{
    char* qb = SMD + q * SM_QUARTER;
    u32 qb32 = (u32)__cvta_generic_to_shared(qb);
    int lid = threadIdx.x & 127;
    int tx = lid & 7, ty = lid >> 3;          // 8 x 16: rows ty, ty+16

    int colT = (Ncols + 63) >> 6;
    int rowT = (M + 31) >> 5;
    int TT   = colT * rowT * batches * KSPLIT;
    int Klen = K / KSPLIT;
    int nkt  = (Klen + 63) >> 6;

    for (int t = qid; t < TT; t += NSTREAM) {
        int ks = (KSPLIT == 2) ? (t & 1) : 0;
        int t2 = (KSPLIT == 2) ? (t >> 1) : t;
        int bz  = t2 / (colT * rowT);
        int r2  = t2 - bz * (colT * rowT);
        int byy = r2 / colT, bxx = r2 - byy * colT;
        int row0 = byy * 32, col0 = bxx * 64;
        int kbase = ks * Klen;
        int kend  = kbase + Klen;

        const float* Ab = A + (long long)bz * sA;
        const float* Bb;
        int colB;
        if (BVIEW) { Bb = B + (col0 >= 64 ? MEMD * 64 : 0); colB = col0 & 63; }
        else       { Bb = B + (long long)bz * sB;           colB = col0; }
        float* Cb = (ks ? C1 : C0) + (long long)bz * sC;

        auto issue = [&](int stage, int kt) {
            u32 sb = qb32 + stage * SM_STAGE;
            int kg = kbase + kt * 64;
            #pragma unroll
            for (int g = 0; g < 8; g++) {          // A: 32 rows x 64 k, 8B chunks
                int idx = lid + g * 128;
                int rr = idx >> 5, kc = (idx & 31) * 2;
                int k = kg + kc;
                bool p = (k < kend) && (row0 + rr < M);
                cpa8(sb + rr * 264 + kc * 4,
                     Ab + (long long)(row0 + rr) * ldA + k, p);
            }
            #pragma unroll
            for (int g = 0; g < 8; g++) {          // B: 64 k x 64 cols, 16B chunks
                int idx = lid + g * 128;
                int kk = idx >> 4, c4 = (idx & 15) * 4;
                int k = kg + kk;
                bool p = (k < kend) && (col0 + c4 < Ncols);
                cpa16(sb + SM_A_BYTES + kk * 256 + c4 * 4,
                      Bb + (long long)k * ldB + colB + c4, p);
            }
            cpa_commit();
        };

        issue(0, 0);

        u64 acc0 = 0, acc1 = 0, acc2 = 0, acc3 = 0;
        u64 acc4 = 0, acc5 = 0, acc6 = 0, acc7 = 0;

        for (int kt = 0; kt < nkt; kt++) {
            bool more = (kt + 1 < nkt);
            if (more) issue((kt + 1) & 1, kt + 1);
            if (more) cpa_wait1(); else cpa_wait0();
            qbar(q);

            const float* Asf = (const float*)(qb + (kt & 1) * SM_STAGE);
            const float* Bsf = Asf + SM_A_BYTES / 4;
            #pragma unroll 8
            for (int kp = 0; kp < 32; kp++) {
                float2 a0 = *(const float2*)&Asf[ty * 66 + kp * 2];
                float2 a1 = *(const float2*)&Asf[(ty + 16) * 66 + kp * 2];
                u64 b00a, b00b, b01a, b01b, b10a, b10b, b11a, b11b;
                lds_v2u64(b00a, b00b, &Bsf[(kp * 2) * 64 + tx * 4]);
                lds_v2u64(b01a, b01b, &Bsf[(kp * 2) * 64 + 32 + tx * 4]);
                lds_v2u64(b10a, b10b, &Bsf[(kp * 2 + 1) * 64 + tx * 4]);
                lds_v2u64(b11a, b11b, &Bsf[(kp * 2 + 1) * 64 + 32 + tx * 4]);
                u64 ax0 = packff(a0.x, a0.x), ax1 = packff(a1.x, a1.x);
                u64 ay0 = packff(a0.y, a0.y), ay1 = packff(a1.y, a1.y);
                fma2(acc0, ax0, b00a); fma2(acc1, ax0, b00b);
                fma2(acc2, ax0, b01a); fma2(acc3, ax0, b01b);
                fma2(acc4, ax1, b00a); fma2(acc5, ax1, b00b);
                fma2(acc6, ax1, b01a); fma2(acc7, ax1, b01b);
                fma2(acc0, ay0, b10a); fma2(acc1, ay0, b10b);
                fma2(acc2, ay0, b11a); fma2(acc3, ay0, b11b);
                fma2(acc4, ay1, b10a); fma2(acc5, ay1, b10b);
                fma2(acc6, ay1, b11a); fma2(acc7, ay1, b11b);
            }
            qbar(q);
        }

        // epilogue: rows ty, ty+16; cols col0 + g*32 + tx*4 + {0..3}
        u64 accs[8] = {acc0, acc1, acc2, acc3, acc4, acc5, acc6, acc7};
        #pragma unroll
        for (int r = 0; r < 2; r++) {
            int row = row0 + ty + r * 16;
            if (row >= M) continue;
            #pragma unroll
            for (int g = 0; g < 2; g++) {
                int cbase = col0 + g * 32 + tx * 4;
                float2 lo = unpk(accs[r * 4 + g * 2]);
                float2 hi = unpk(accs[r * 4 + g * 2 + 1]);
                float v[4] = {lo.x, lo.y, hi.x, hi.y};
                #pragma unroll
                for (int j = 0; j < 4; j++) {
                    int cc = cbase + j;
                    if (cc < Ncols) {
                        float bv = bias ? bias[cc] : 0.f;
                        Cb[(long long)row * ldC + cc] = v[j] + bv;
                    }
                }
            }
        }
    }
}

// ---------------- combineHS: g_hs = q0 + q1 + bias ---------------------------
__device__ void combineHS(const float* __restrict__ bias)
{
    const int TOT = NB * NN * CDIM;
    int tid = threadIdx.x;
    for (int i = blockIdx.x * NTHR + tid; i < TOT; i += GRIDSZ * NTHR) {
        int c = i % CDIM;
        g_hs[i] = g_q0[i] + g_q1[i] + bias[c];
    }
}

// ---------------- pairwise: p = adj*exp(leaky(e)), partial Z -----------------
// e = 0.5*(ci + dj + sum_h w_h*|si_h + sj_h|) + a2b   (relu(x) = (x+|x|)/2)
// each thread: rows (ty, ty+16), 4 CONSECUTIVE cols tx*4..tx*4+3 (float4 path)
__device__ void pair_phase(char* SMD,
                           const float* __restrict__ adj,
                           const float* __restrict__ a2w,
                           const float* __restrict__ a2b)
{
    float2 (*SiT2)[17]  = (float2(*)[17])SMD;                 // [64][17]
    float  (*SjT)[132]  = (float(*)[132])(SMD + SM_SJ);       // [64][132] pad
    float* W   = (float*)(SMD + SM_W);
    float* red = (float*)(SMD + SM_RED);
    float2* cvi = (float2*)(SMD + SM_CVI);    // [16] rank-1 i-terms
    float*  cvj = (float*)(SMD + SM_CVJ);     // [128] rank-1 j-terms

    int tid = threadIdx.x;
    int tx = tid & 31, ty = (tid >> 5) & 15;
    const int Tt = NB * (NN / TI) * (NN / TJ);   // 128

    for (int t = blockIdx.x; t < Tt; t += GRIDSZ) {
        int b = t >> 6;
        int rem = t & 63;
        int by = rem >> 2, bx = rem & 3;
        int i0 = by * TI, j0 = bx * TJ;

        __syncthreads();
        for (int idx = tid; idx < HIDD * 16; idx += NTHR) {
            int h = idx & 63, rr = idx >> 6;
            float u0 = g_hs[((long long)(b * NN) + i0 + rr) * CDIM + 300 + h];
            float u1 = g_hs[((long long)(b * NN) + i0 + rr + 16) * CDIM + 300 + h];
            SiT2[h][rr] = make_float2(u0, u1);
        }
        for (int idx = tid; idx < HIDD * TJ; idx += NTHR) {
            int h = idx & 63, rr = idx >> 6;
            SjT[h][rr] = g_hs[((long long)(b * NN) + j0 + rr) * CDIM + 364 + h];
        }
        if (tid < HIDD) W[tid] = a2w[tid];
        __syncthreads();

        // rank-1 prologue: dj (128 dots, tid<128) + ci (16 f2 dots, tid 128..143)
        if (tid < 128) {
            float s = 0.f;
            #pragma unroll 8
            for (int h = 0; h < HIDD; h++) s += W[h] * SjT[h][tid];
            cvj[tid] = s;
        } else if (tid < 144) {
            int r = tid - 128;                // r in [0,16)
            float sx = 0.f, sy = 0.f;
            #pragma unroll 8
            for (int h = 0; h < HIDD; h++) {
                float2 v = SiT2[h][r];
                float w = W[h];
                sx += w * v.x; sy += w * v.y;
            }
            cvi[r] = make_float2(sx, sy);
        }
        __syncthreads();

        float acc[8] = {0.f, 0.f, 0.f, 0.f, 0.f, 0.f, 0.f, 0.f};
        #pragma unroll 8
        for (int h = 0; h < HIDD; h++) {
            float w = W[h];
            float2 ai = SiT2[h][ty];
            float4 bj = *(const float4*)&SjT[h][tx * 4];
            float bjv[4] = {bj.x, bj.y, bj.z, bj.w};
            #pragma unroll
            for (int jj = 0; jj < 4; jj++) {
                acc[jj]     += w * fabsf(ai.x + bjv[jj]);
                acc[4 + jj] += w * fabsf(ai.y + bjv[jj]);
            }
        }

        float a2bv = a2b[0];
        float2 civ = cvi[ty];
        int ia = i0 + ty, ib = i0 + ty + 16;
        int jb = j0 + tx * 4;
        float4 dj4 = *(const float4*)&cvj[tx * 4];
        float djv[4] = {dj4.x, dj4.y, dj4.z, dj4.w};
        float4 ad0 = *(const float4*)&adj[((long long)b * NN + ia) * NN + jb];
        float4 ad1 = *(const float4*)&adj[((long long)b * NN + ib) * NN + jb];
        float adv0[4] = {ad0.x, ad0.y, ad0.z, ad0.w};
        float adv1[4] = {ad1.x, ad1.y, ad1.z, ad1.w};
        float p0v[4], p1v[4];
        float psum = 0.f;
        #pragma unroll
        for (int jj = 0; jj < 4; jj++) {
            float e0 = 0.5f * (acc[jj]     + civ.x + djv[jj]) + a2bv;
            float e1 = 0.5f * (acc[4 + jj] + civ.y + djv[jj]) + a2bv;
            e0 = e0 > 0.f ? e0 : NEG_SLOPE * e0;
            e1 = e1 > 0.f ? e1 : NEG_SLOPE * e1;
            p0v[jj] = adv0[jj] * __expf(e0);
            p1v[jj] = adv1[jj] * __expf(e1);
            psum += p0v[jj] + p1v[jj];
        }
        *(float4*)&g_p[((long long)b * NN + ia) * NN + jb] =
            make_float4(p0v[0], p0v[1], p0v[2], p0v[3]);
        *(float4*)&g_p[((long long)b * NN + ib) * NN + jb] =
            make_float4(p1v[0], p1v[1], p1v[2], p1v[3]);

        red[tid] = psum;
        __syncthreads();
        for (int s = 256; s > 0; s >>= 1) {
            if (tid < s) red[tid] += red[tid + s];
            __syncthreads();
        }
        if (tid == 0) g_partial[b * 64 + rem] = red[0];
    }
}

// ---------------- combine: dst = (q0+q1) * invZ[b]  (out-GEMM partials) ------
__device__ void combine_phase(char* SMD, const float* __restrict__ q0,
                              const float* __restrict__ q1,
                              float* __restrict__ dst)
{
    float* invZ = (float*)(SMD + SM_INVZ);
    int tid = threadIdx.x;
    if (tid < NB) {
        float s = 0.f;
        #pragma unroll
        for (int k = 0; k < 64; k++) s += g_partial[tid * 64 + k];
        invZ[tid] = 1.f / s;
    }
    __syncthreads();
    float z0 = invZ[0], z1 = invZ[1];
    const int TOT = NB * NN * MEMD;
    for (int i = blockIdx.x * NTHR + tid; i < TOT; i += GRIDSZ * NTHR) {
        float z = (i < NN * MEMD) ? z0 : z1;
        dst[i] = (q0[i] + q1[i]) * z;
    }
}

// ---------------- the one persistent kernel ----------------------------------
__global__ void __launch_bounds__(NTHR, 1) fused_gat(
    const float* __restrict__ feature, const float* __restrict__ adj,
    const float* __restrict__ w0, const float* __restrict__ b0,
    const float* __restrict__ w1, const float* __restrict__ b1,
    const float* __restrict__ a1w, const float* __restrict__ a1b,
    const float* __restrict__ a2w, const float* __restrict__ a2b,
    float* __restrict__ out)
{
    extern __shared__ char SMD[];
    __shared__ unsigned s_base;
    if (threadIdx.x == 0) s_base = *(volatile unsigned*)&g_bar_gen;
    __syncthreads();
    unsigned bb = s_base;
    int q   = threadIdx.x >> 7;               // quarter 0..3
    int qid = q * GRIDSZ + blockIdx.x;        // 0..591
    int tid = threadIdx.x;

    // ======== P0: B' = [W | W@a1w-packed], bias vectors ========
    for (int idx = blockIdx.x * NTHR + tid; idx < IND * MEMD; idx += GRIDSZ * NTHR) {
        int r = idx / MEMD, c = idx - r * MEMD;
        g_B1[r * CDIM + c] = w0[idx];
    }
    for (int idx = blockIdx.x * NTHR + tid; idx < MEMD * MEMD; idx += GRIDSZ * NTHR) {
        int r = idx / MEMD, c = idx - r * MEMD;
        g_B2[r * CDIM + c] = w1[idx];
    }
    if (blockIdx.x < 2) {
        const float* bsrc = blockIdx.x ? b1 : b0;
        float* bd = blockIdx.x ? g_bias2 : g_bias1;
        for (int c = tid; c < MEMD; c += NTHR) bd[c] = bsrc[c];
        if (tid < 128) {
            float acc = 0.f;
            for (int k = 0; k < MEMD; k++) {
                float w = (tid < 64) ? a1w[k * 64 + tid]
                                     : a1w[(MEMD + k) * 64 + (tid - 64)];
                acc += bsrc[k] * w;
            }
            bd[300 + tid] = acc + ((tid >= 64) ? a1b[tid - 64] : 0.f);
        }
    }
    // Wp0 on low quarters, Wp1 on high quarters (disjoint)
    gemm_cp<1, 1>(SMD, q, qid, w0, 0, MEMD, a1w, 0, 64,
                  g_B1 + 300, nullptr, 0, CDIM, IND, 128, MEMD, 1, nullptr);
    gemm_cp<1, 1>(SMD, q, (NSTREAM - 1) - qid, w1, 0, MEMD, a1w, 0, 64,
                  g_B2 + 300, nullptr, 0, CDIM, MEMD, 128, MEMD, 1, nullptr);
    grid_bar(bb + 1);

    // ======== layer 1 ========
    gemm_cp<0, 2>(SMD, q, qid, feature, 0, IND, g_B1, 0, CDIM,
                  g_q0, g_q1, 0, CDIM, NB * NN, CDIM, IND, 1, nullptr);
    grid_bar(bb + 2);
    combineHS(g_bias1);
    grid_bar(bb + 3);
    pair_phase(SMD, adj, a2w, a2b);
    grid_bar(bb + 4);
    gemm_cp<0, 2>(SMD, q, qid, g_p, (long long)NN * NN, NN,
                  g_hs, (long long)NN * CDIM, CDIM,
                  g_q0, g_q1, (long long)NN * MEMD, MEMD,
                  NN, MEMD, NN, NB, nullptr);
    grid_bar(bb + 5);
    combine_phase(SMD, g_q0, g_q1, g_out1);
    grid_bar(bb + 6);

    // ======== layer 2 ========
    gemm_cp<0, 2>(SMD, q, qid, g_out1, 0, MEMD, g_B2, 0, CDIM,
                  g_q0, g_q1, 0, CDIM, NB * NN, CDIM, MEMD, 1, nullptr);
    grid_bar(bb + 7);
    combineHS(g_bias2);
    grid_bar(bb + 8);
    pair_phase(SMD, adj, a2w, a2b);
    grid_bar(bb + 9);
    gemm_cp<0, 2>(SMD, q, qid, g_p, (long long)NN * NN, NN,
                  g_hs, (long long)NN * CDIM, CDIM,
                  g_q0, g_q1, (long long)NN * MEMD, MEMD,
                  NN, MEMD, NN, NB, nullptr);
    grid_bar(bb + 10);
    combine_phase(SMD, g_q0, g_q1, out);
}

// ---------------- host launcher ----------------------------------------------
extern "C" void kernel_launch(void* const* d_in, const int* in_sizes, int n_in,
                              void* d_out, int out_size)
{
    const float* feature = (const float*)d_in[0];
    const float* adj     = (const float*)d_in[1];
    const float* w0      = (const float*)d_in[2];
    const float* b0      = (const float*)d_in[3];
    const float* w1      = (const float*)d_in[4];
    const float* b1      = (const float*)d_in[5];
    const float* a1w     = (const float*)d_in[6];
    const float* a1b     = (const float*)d_in[7];
    const float* a2w     = (const float*)d_in[8];
    const float* a2b     = (const float*)d_in[9];
    float* out = (float*)d_out;

    static bool attr_set = false;
    if (!attr_set) {
        cudaFuncSetAttribute(fused_gat,
                             cudaFuncAttributeMaxDynamicSharedMemorySize, SM_DYN);
        attr_set = true;
    }
    fused_gat<<<GRIDSZ, NTHR, SM_DYN>>>(feature, adj, w0, b0, w1, b1,
                                        a1w, a1b, a2w, a2b, out);
}

// round 16
// speedup vs baseline: 1.3384x; 1.0890x over previous
#include <cuda_runtime.h>

typedef unsigned int       u32;
typedef unsigned long long u64;

#define NB   2
#define NN   512
#define IND  512
#define MEMD 300
#define HIDD 64
#define CDIM 428
#define NEG_SLOPE 0.01f
#define GRIDSZ 148
#define NTHR 512
#define NSTREAM (4 * GRIDSZ)      // 128-thread quarter streams
#define TI 32
#define TJ 128

// ---------------- scratch (allocation-free: __device__ globals) -------------
__device__ float g_B1[IND * CDIM];        // [w0 | Wp0]
__device__ float g_B2[MEMD * CDIM];       // [w1 | Wp1]
__device__ float g_bias1[CDIM];
__device__ float g_bias2[CDIM];
__device__ float g_hs[NB * NN * CDIM];    // [h(300) | si(64) | sj(64)]
__device__ float g_q0[NB * NN * CDIM];    // K-split partials
__device__ float g_q1[NB * NN * CDIM];
__device__ float g_p[NB * NN * NN];
__device__ float g_partial[NB * 64];
__device__ unsigned g_bar_count;          // zero-init
__device__ unsigned g_bar_gen;            // monotonic across replays

// ---------------- grid-wide barrier (replay-safe; R10-proven) ----------------
__device__ __forceinline__ void grid_bar(unsigned target)
{
    __threadfence();
    __syncthreads();
    if (threadIdx.x == 0) {
        if (atomicAdd(&g_bar_count, 1u) == GRIDSZ - 1u) {
            g_bar_count = 0u;
            __threadfence();
            *(volatile unsigned*)&g_bar_gen = target;
        } else {
            while ((int)(*(volatile unsigned*)&g_bar_gen - target) < 0) { }
        }
        __threadfence();
    }
    __syncthreads();
}

// per-quarter named barrier (128 threads; ids 1..4)
__device__ __forceinline__ void qbar(int q)
{
    asm volatile("bar.sync %0, 128;" :: "r"(q + 1) : "memory");
}

// ---------------- cp.async + packed f32 helpers ------------------------------
__device__ __forceinline__ void cpa16(u32 dst, const void* src, bool p)
{
    if (p) asm volatile("cp.async.ca.shared.global [%0], [%1], 16;"
                        :: "r"(dst), "l"(src));
    else   asm volatile("st.shared.v4.b32 [%0], {%1,%1,%1,%1};"
                        :: "r"(dst), "r"(0u));
}
__device__ __forceinline__ void cpa8(u32 dst, const void* src, bool p)
{
    if (p) asm volatile("cp.async.ca.shared.global [%0], [%1], 8;"
                        :: "r"(dst), "l"(src));
    else   asm volatile("st.shared.v2.b32 [%0], {%1,%1};"
                        :: "r"(dst), "r"(0u));
}
__device__ __forceinline__ void cpa_commit()
{
    asm volatile("cp.async.commit_group;" ::: "memory");
}
__device__ __forceinline__ void cpa_wait1()
{
    asm volatile("cp.async.wait_group 1;" ::: "memory");
}
__device__ __forceinline__ void cpa_wait0()
{
    asm volatile("cp.async.wait_group 0;" ::: "memory");
}
__device__ __forceinline__ u64 packff(float x, float y)
{
    u64 r;
    asm("mov.b64 %0, {%1, %2};" : "=l"(r)
        : "r"(__float_as_uint(x)), "r"(__float_as_uint(y)));
    return r;
}
__device__ __forceinline__ void fma2(u64& d, u64 a, u64 b)
{
    asm("fma.rn.f32x2 %0, %1, %2, %3;" : "=l"(d) : "l"(a), "l"(b), "l"(d));
}
__device__ __forceinline__ float2 unpk(u64 v)
{
    u32 lo, hi;
    asm("mov.b64 {%0, %1}, %2;" : "=r"(lo), "=r"(hi) : "l"(v));
    return make_float2(__uint_as_float(lo), __uint_as_float(hi));
}
__device__ __forceinline__ void lds_v2u64(u64& x, u64& y, const float* p)
{
    u32 a = (u32)__cvta_generic_to_shared(p);
    asm volatile("ld.shared.v2.b64 {%0, %1}, [%2];"
                 : "=l"(x), "=l"(y) : "r"(a));
}

// ---------------- dynamic smem layout ----------------------------------------
// per quarter: 2 stages x (A 32x66 f = 8448B | B 64x64 f = 16384B) = 49664
// pair overlay (offset 0, spans quarters 0-1):
//   SiT2[64][17]f2 8704 | SjT[64][132] 33792 | W 256 | red 2048 | cvi 128 | cvj 512
#define SM_A_BYTES 8448
#define SM_STAGE   24832
#define SM_QUARTER 49664
#define SM_SJ      8704
#define SM_W       42496
#define SM_RED     42752
#define SM_CVI     44800
#define SM_CVJ     44928
#define SM_INVZ    (4 * SM_QUARTER)
#define SM_DYN     (SM_INVZ + 256)

// ---------------- cp.async GEMM (quarter streams; R10/R13-proven 32x64) ------
// 128-thread quarter computes 32x64 tiles, BK=64, 2-stage pipeline,
// 2x8 micro with packed f32x2 FMAs.
// KSPLIT=2 -> unscaled partials C0/C1.
// AMODE=1  -> A is computed on the fly as (Aq0 + Aq1) * invZ[row>>9]
//             (invZ in smem at SM_INVZ), stored to smem synchronously.
template<int BVIEW, int KSPLIT, int AMODE>
__device__ void gemm_cp(char* SMD, int q, int qid,
                        const float* __restrict__ A, long long sA, int ldA,
                        const float* __restrict__ Aq1,
                        const float* __restrict__ B, long long sB, int ldB,
                        float* __restrict__ C0, float* __restrict__ C1,
                        long long sC, int ldC,
                        int M, int Ncols, int K, int batches,
                        const float* __restrict__ bias)
{
    char* qb = SMD + q * SM_QUARTER;
    u32 qb32 = (u32)__cvta_generic_to_shared(qb);
    const float* invZs = (const float*)(SMD + SM_INVZ);
    int lid = threadIdx.x & 127;
    int tx = lid & 7, ty = lid >> 3;          // 8 x 16: rows ty, ty+16

    int colT = (Ncols + 63) >> 6;
    int rowT = (M + 31) >> 5;
    int TT   = colT * rowT * batches * KSPLIT;
    int Klen = K / KSPLIT;
    int nkt  = (Klen + 63) >> 6;

    for (int t = qid; t < TT; t += NSTREAM) {
        int ks = (KSPLIT == 2) ? (t & 1) : 0;
        int t2 = (KSPLIT == 2) ? (t >> 1) : t;
        int bz  = t2 / (colT * rowT);
        int r2  = t2 - bz * (colT * rowT);
        int byy = r2 / colT, bxx = r2 - byy * colT;
        int row0 = byy * 32, col0 = bxx * 64;
        int kbase = ks * Klen;
        int kend  = kbase + Klen;

        const float* Ab = A + (long long)bz * sA;
        const float* Bb;
        int colB;
        if (BVIEW) { Bb = B + (col0 >= 64 ? MEMD * 64 : 0); colB = col0 & 63; }
        else       { Bb = B + (long long)bz * sB;           colB = col0; }
        float* Cb = (ks ? C1 : C0) + (long long)bz * sC;

        auto issue = [&](int stage, int kt) {
            u32 sb = qb32 + stage * SM_STAGE;
            int kg = kbase + kt * 64;
            // B first (async) so AMODE1's synchronous A overlaps its fetch
            #pragma unroll
            for (int g = 0; g < 8; g++) {          // B: 64 k x 64 cols, 16B chunks
                int idx = lid + g * 128;
                int kk = idx >> 4, c4 = (idx & 15) * 4;
                int k = kg + kk;
                bool p = (k < kend) && (col0 + c4 < Ncols);
                cpa16(sb + SM_A_BYTES + kk * 256 + c4 * 4,
                      Bb + (long long)k * ldB + colB + c4, p);
            }
            #pragma unroll
            for (int g = 0; g < 8; g++) {          // A: 32 rows x 64 k, 8B chunks
                int idx = lid + g * 128;
                int rr = idx >> 5, kc = (idx & 31) * 2;
                int k = kg + kc;
                bool pv = (k < kend) && (row0 + rr < M);
                if (AMODE == 0) {
                    cpa8(sb + rr * 264 + kc * 4,
                         Ab + (long long)(row0 + rr) * ldA + k, pv);
                } else {
                    float2 v = make_float2(0.f, 0.f);
                    if (pv) {
                        long long off = (long long)(row0 + rr) * ldA + k;
                        float2 x0 = *(const float2*)(Ab + off);
                        float2 x1 = *(const float2*)(Aq1 + off);
                        float z = invZs[(row0 + rr) >> 9];
                        v = make_float2((x0.x + x1.x) * z, (x0.y + x1.y) * z);
                    }
                    *(float2*)(qb + stage * SM_STAGE + rr * 264 + kc * 4) = v;
                }
            }
            cpa_commit();
        };

        issue(0, 0);

        u64 acc0 = 0, acc1 = 0, acc2 = 0, acc3 = 0;
        u64 acc4 = 0, acc5 = 0, acc6 = 0, acc7 = 0;

        for (int kt = 0; kt < nkt; kt++) {
            bool more = (kt + 1 < nkt);
            if (more) issue((kt + 1) & 1, kt + 1);
            if (more) cpa_wait1(); else cpa_wait0();
            qbar(q);

            const float* Asf = (const float*)(qb + (kt & 1) * SM_STAGE);
            const float* Bsf = Asf + SM_A_BYTES / 4;
            #pragma unroll 8
            for (int kp = 0; kp < 32; kp++) {
                float2 a0 = *(const float2*)&Asf[ty * 66 + kp * 2];
                float2 a1 = *(const float2*)&Asf[(ty + 16) * 66 + kp * 2];
                u64 b00a, b00b, b01a, b01b, b10a, b10b, b11a, b11b;
                lds_v2u64(b00a, b00b, &Bsf[(kp * 2) * 64 + tx * 4]);
                lds_v2u64(b01a, b01b, &Bsf[(kp * 2) * 64 + 32 + tx * 4]);
                lds_v2u64(b10a, b10b, &Bsf[(kp * 2 + 1) * 64 + tx * 4]);
                lds_v2u64(b11a, b11b, &Bsf[(kp * 2 + 1) * 64 + 32 + tx * 4]);
                u64 ax0 = packff(a0.x, a0.x), ax1 = packff(a1.x, a1.x);
                u64 ay0 = packff(a0.y, a0.y), ay1 = packff(a1.y, a1.y);
                fma2(acc0, ax0, b00a); fma2(acc1, ax0, b00b);
                fma2(acc2, ax0, b01a); fma2(acc3, ax0, b01b);
                fma2(acc4, ax1, b00a); fma2(acc5, ax1, b00b);
                fma2(acc6, ax1, b01a); fma2(acc7, ax1, b01b);
                fma2(acc0, ay0, b10a); fma2(acc1, ay0, b10b);
                fma2(acc2, ay0, b11a); fma2(acc3, ay0, b11b);
                fma2(acc4, ay1, b10a); fma2(acc5, ay1, b10b);
                fma2(acc6, ay1, b11a); fma2(acc7, ay1, b11b);
            }
            qbar(q);
        }

        // epilogue: rows ty, ty+16; cols col0 + g*32 + tx*4 + {0..3}
        u64 accs[8] = {acc0, acc1, acc2, acc3, acc4, acc5, acc6, acc7};
        #pragma unroll
        for (int r = 0; r < 2; r++) {
            int row = row0 + ty + r * 16;
            if (row >= M) continue;
            #pragma unroll
            for (int g = 0; g < 2; g++) {
                int cbase = col0 + g * 32 + tx * 4;
                float2 lo = unpk(accs[r * 4 + g * 2]);
                float2 hi = unpk(accs[r * 4 + g * 2 + 1]);
                float v[4] = {lo.x, lo.y, hi.x, hi.y};
                #pragma unroll
                for (int j = 0; j < 4; j++) {
                    int cc = cbase + j;
                    if (cc < Ncols) {
                        float bv = bias ? bias[cc] : 0.f;
                        Cb[(long long)row * ldC + cc] = v[j] + bv;
                    }
                }
            }
        }
    }
}

// ---------------- pairwise: p = adj*exp(leaky(e)), partial Z -----------------
// e = 0.5*(ci + dj + sum_h w_h*|si_h + sj_h|) + a2b   (relu(x) = (x+|x|)/2)
// each thread: rows (ty, ty+16), 4 CONSECUTIVE cols tx*4..tx*4+3 (float4 path)
__device__ void pair_phase(char* SMD,
                           const float* __restrict__ adj,
                           const float* __restrict__ a2w,
                           const float* __restrict__ a2b)
{
    float2 (*SiT2)[17]  = (float2(*)[17])SMD;                 // [64][17]
    float  (*SjT)[132]  = (float(*)[132])(SMD + SM_SJ);       // [64][132] pad
    float* W   = (float*)(SMD + SM_W);
    float* red = (float*)(SMD + SM_RED);
    float2* cvi = (float2*)(SMD + SM_CVI);    // [16] rank-1 i-terms
    float*  cvj = (float*)(SMD + SM_CVJ);     // [128] rank-1 j-terms

    int tid = threadIdx.x;
    int tx = tid & 31, ty = (tid >> 5) & 15;
    const int Tt = NB * (NN / TI) * (NN / TJ);   // 128

    for (int t = blockIdx.x; t < Tt; t += GRIDSZ) {
        int b = t >> 6;
        int rem = t & 63;
        int by = rem >> 2, bx = rem & 3;
        int i0 = by * TI, j0 = bx * TJ;

        __syncthreads();
        for (int idx = tid; idx < HIDD * 16; idx += NTHR) {
            int h = idx & 63, rr = idx >> 6;
            float u0 = g_hs[((long long)(b * NN) + i0 + rr) * CDIM + 300 + h];
            float u1 = g_hs[((long long)(b * NN) + i0 + rr + 16) * CDIM + 300 + h];
            SiT2[h][rr] = make_float2(u0, u1);
        }
        for (int idx = tid; idx < HIDD * TJ; idx += NTHR) {
            int h = idx & 63, rr = idx >> 6;
            SjT[h][rr] = g_hs[((long long)(b * NN) + j0 + rr) * CDIM + 364 + h];
        }
        if (tid < HIDD) W[tid] = a2w[tid];
        __syncthreads();

        // rank-1 prologue: dj (128 dots, tid<128) + ci (16 f2 dots, tid 128..143)
        if (tid < 128) {
            float s = 0.f;
            #pragma unroll 8
            for (int h = 0; h < HIDD; h++) s += W[h] * SjT[h][tid];
            cvj[tid] = s;
        } else if (tid < 144) {
            int r = tid - 128;                // r in [0,16)
            float sx = 0.f, sy = 0.f;
            #pragma unroll 8
            for (int h = 0; h < HIDD; h++) {
                float2 v = SiT2[h][r];
                float w = W[h];
                sx += w * v.x; sy += w * v.y;
            }
            cvi[r] = make_float2(sx, sy);
        }
        __syncthreads();

        float acc[8] = {0.f, 0.f, 0.f, 0.f, 0.f, 0.f, 0.f, 0.f};
        #pragma unroll 8
        for (int h = 0; h < HIDD; h++) {
            float w = W[h];
            float2 ai = SiT2[h][ty];
            float4 bj = *(const float4*)&SjT[h][tx * 4];
            float bjv[4] = {bj.x, bj.y, bj.z, bj.w};
            #pragma unroll
            for (int jj = 0; jj < 4; jj++) {
                acc[jj]     += w * fabsf(ai.x + bjv[jj]);
                acc[4 + jj] += w * fabsf(ai.y + bjv[jj]);
            }
        }

        float a2bv = a2b[0];
        float2 civ = cvi[ty];
        int ia = i0 + ty, ib = i0 + ty + 16;
        int jb = j0 + tx * 4;
        float4 dj4 = *(const float4*)&cvj[tx * 4];
        float djv[4] = {dj4.x, dj4.y, dj4.z, dj4.w};
        float4 ad0 = *(const float4*)&adj[((long long)b * NN + ia) * NN + jb];
        float4 ad1 = *(const float4*)&adj[((long long)b * NN + ib) * NN + jb];
        float adv0[4] = {ad0.x, ad0.y, ad0.z, ad0.w};
        float adv1[4] = {ad1.x, ad1.y, ad1.z, ad1.w};
        float p0v[4], p1v[4];
        float psum = 0.f;
        #pragma unroll
        for (int jj = 0; jj < 4; jj++) {
            float e0 = 0.5f * (acc[jj]     + civ.x + djv[jj]) + a2bv;
            float e1 = 0.5f * (acc[4 + jj] + civ.y + djv[jj]) + a2bv;
            e0 = e0 > 0.f ? e0 : NEG_SLOPE * e0;
            e1 = e1 > 0.f ? e1 : NEG_SLOPE * e1;
            p0v[jj] = adv0[jj] * __expf(e0);
            p1v[jj] = adv1[jj] * __expf(e1);
            psum += p0v[jj] + p1v[jj];
        }
        *(float4*)&g_p[((long long)b * NN + ia) * NN + jb] =
            make_float4(p0v[0], p0v[1], p0v[2], p0v[3]);
        *(float4*)&g_p[((long long)b * NN + ib) * NN + jb] =
            make_float4(p1v[0], p1v[1], p1v[2], p1v[3]);

        red[tid] = psum;
        __syncthreads();
        for (int s = 256; s > 0; s >>= 1) {
            if (tid < s) red[tid] += red[tid + s];
            __syncthreads();
        }
        if (tid == 0) g_partial[b * 64 + rem] = red[0];
    }
}

// ---------------- invZ -> smem (per block, deterministic) --------------------
__device__ void compute_invZ(char* SMD)
{
    float* invZ = (float*)(SMD + SM_INVZ);
    int tid = threadIdx.x;
    if (tid < NB) {
        float s = 0.f;
        #pragma unroll
        for (int k = 0; k < 64; k++) s += g_partial[tid * 64 + k];
        invZ[tid] = 1.f / s;
    }
    __syncthreads();
}

// ---------------- final combine: dst = (q0+q1) * invZ[b] ---------------------
__device__ void combine_phase(char* SMD, const float* __restrict__ q0,
                              const float* __restrict__ q1,
                              float* __restrict__ dst)
{
    compute_invZ(SMD);
    float* invZ = (float*)(SMD + SM_INVZ);
    float z0 = invZ[0], z1 = invZ[1];
    int tid = threadIdx.x;
    const int TOT = NB * NN * MEMD;
    for (int i = blockIdx.x * NTHR + tid; i < TOT; i += GRIDSZ * NTHR) {
        float z = (i < NN * MEMD) ? z0 : z1;
        dst[i] = (q0[i] + q1[i]) * z;
    }
}

// ---------------- the one persistent kernel ----------------------------------
__global__ void __launch_bounds__(NTHR, 1) fused_gat(
    const float* __restrict__ feature, const float* __restrict__ adj,
    const float* __restrict__ w0, const float* __restrict__ b0,
    const float* __restrict__ w1, const float* __restrict__ b1,
    const float* __restrict__ a1w, const float* __restrict__ a1b,
    const float* __restrict__ a2w, const float* __restrict__ a2b,
    float* __restrict__ out)
{
    extern __shared__ char SMD[];
    __shared__ unsigned s_base;
    if (threadIdx.x == 0) s_base = *(volatile unsigned*)&g_bar_gen;
    __syncthreads();
    unsigned bb = s_base;
    int q   = threadIdx.x >> 7;               // quarter 0..3
    int qid = q * GRIDSZ + blockIdx.x;        // 0..591
    int tid = threadIdx.x;

    // ======== P0: B' = [W | W@a1w-packed], bias vectors ========
    for (int idx = blockIdx.x * NTHR + tid; idx < IND * MEMD; idx += GRIDSZ * NTHR) {
        int r = idx / MEMD, c = idx - r * MEMD;
        g_B1[r * CDIM + c] = w0[idx];
    }
    for (int idx = blockIdx.x * NTHR + tid; idx < MEMD * MEMD; idx += GRIDSZ * NTHR) {
        int r = idx / MEMD, c = idx - r * MEMD;
        g_B2[r * CDIM + c] = w1[idx];
    }
    if (blockIdx.x < 2) {
        const float* bsrc = blockIdx.x ? b1 : b0;
        float* bd = blockIdx.x ? g_bias2 : g_bias1;
        for (int c = tid; c < MEMD; c += NTHR) bd[c] = bsrc[c];
        if (tid < 128) {
            float acc = 0.f;
            for (int k = 0; k < MEMD; k++) {
                float w = (tid < 64) ? a1w[k * 64 + tid]
                                     : a1w[(MEMD + k) * 64 + (tid - 64)];
                acc += bsrc[k] * w;
            }
            bd[300 + tid] = acc + ((tid >= 64) ? a1b[tid - 64] : 0.f);
        }
    }
    // Wp0 on low quarters, Wp1 on high quarters (disjoint)
    gemm_cp<1, 1, 0>(SMD, q, qid, w0, 0, MEMD, nullptr, a1w, 0, 64,
                     g_B1 + 300, nullptr, 0, CDIM, IND, 128, MEMD, 1, nullptr);
    gemm_cp<1, 1, 0>(SMD, q, (NSTREAM - 1) - qid, w1, 0, MEMD, nullptr, a1w, 0, 64,
                     g_B2 + 300, nullptr, 0, CDIM, MEMD, 128, MEMD, 1, nullptr);
    grid_bar(bb + 1);

    // ======== layer 1 ========
    gemm_cp<0, 1, 0>(SMD, q, qid, feature, 0, IND, nullptr, g_B1, 0, CDIM,
                     g_hs, nullptr, 0, CDIM, NB * NN, CDIM, IND, 1, g_bias1);
    grid_bar(bb + 2);
    pair_phase(SMD, adj, a2w, a2b);
    grid_bar(bb + 3);
    gemm_cp<0, 2, 0>(SMD, q, qid, g_p, (long long)NN * NN, NN, nullptr,
                     g_hs, (long long)NN * CDIM, CDIM,
                     g_q0, g_q1, (long long)NN * MEMD, MEMD,
                     NN, MEMD, NN, NB, nullptr);
    grid_bar(bb + 4);

    // ======== layer 2 (G2 consumes (q0+q1)*invZ inline — no combine pass) ====
    compute_invZ(SMD);
    gemm_cp<0, 1, 1>(SMD, q, qid, g_q0, 0, MEMD, g_q1, g_B2, 0, CDIM,
                     g_hs, nullptr, 0, CDIM, NB * NN, CDIM, MEMD, 1, g_bias2);
    grid_bar(bb + 5);
    pair_phase(SMD, adj, a2w, a2b);
    grid_bar(bb + 6);
    gemm_cp<0, 2, 0>(SMD, q, qid, g_p, (long long)NN * NN, NN, nullptr,
                     g_hs, (long long)NN * CDIM, CDIM,
                     g_q0, g_q1, (long long)NN * MEMD, MEMD,
                     NN, MEMD, NN, NB, nullptr);
    grid_bar(bb + 7);
    combine_phase(SMD, g_q0, g_q1, out);
}

// ---------------- host launcher ----------------------------------------------
extern "C" void kernel_launch(void* const* d_in, const int* in_sizes, int n_in,
                              void* d_out, int out_size)
{
    const float* feature = (const float*)d_in[0];
    const float* adj     = (const float*)d_in[1];
    const float* w0      = (const float*)d_in[2];
    const float* b0      = (const float*)d_in[3];
    const float* w1      = (const float*)d_in[4];
    const float* b1      = (const float*)d_in[5];
    const float* a1w     = (const float*)d_in[6];
    const float* a1b     = (const float*)d_in[7];
    const float* a2w     = (const float*)d_in[8];
    const float* a2b     = (const float*)d_in[9];
    float* out = (float*)d_out;

    static bool attr_set = false;
    if (!attr_set) {
        cudaFuncSetAttribute(fused_gat,
                             cudaFuncAttributeMaxDynamicSharedMemorySize, SM_DYN);
        attr_set = true;
    }
    fused_gat<<<GRIDSZ, NTHR, SM_DYN>>>(feature, adj, w0, b0, w1, b1,
                                        a1w, a1b, a2w, a2b, out);
}